// round 11
// baseline (speedup 1.0000x reference)
#include <cuda_runtime.h>
#include <cstdint>

// Sparse 3D conv, persistent-CTA 3-deep pipelined (mma.sync tf32; tcgen05 PTX
// rejected by harness's compute_103 target).
// out[out_map[k,m]] += feats[in_map[k,m]] @ kernel[k]
// N=200000, K=27, M=50000, Cin=Cout=64, fp32 in/out, tf32(RNA at LDS) MMA.
//
// R10: quarter-tile (k=16) stages, 3 A-buffers, gather issued 2 stages ahead
// (wait_group 1) -> gather latency gets two compute phases to hide under.
// 256-thread CTAs, TILE_M=128, 50.2 KB smem -> 4 CTAs/SM.

#define KOFF    27
#define MPAIRS  50000
#define NVOX    200000
#define CIN     64
#define COUT    64
#define TILE_M  128
#define NTHREADS 256
#define TPK     391                 // ceil(50000/128)
#define NTILES  (KOFF * TPK)        // 10557
#define NCTA    608                 // 4 per SM on 152-SM GB300
#define QT      17                  // 10557 = 608*17 + 221
#define RT      221
#define ASTRIDE 20                  // words per row in quarter-buffer (16 + 4 pad)

#define ABUF_WORDS (TILE_M * ASTRIDE)          // 2560 words per buffer
#define OFF_B      (3 * ABUF_WORDS)            // 7680: fragment-packed W^T (4096 w)
#define OFF_IDX    (OFF_B + CIN * COUT)        // 11776: IDX[3][128]
#define OFF_OMAP   (OFF_IDX + 3 * TILE_M)      // 12160: OMAP[3][128]
#define SMEM_WORDS (OFF_OMAP + 3 * TILE_M)     // 12544 words = 50176 B

__device__ __forceinline__ uint32_t f2tf32(float f) {
    uint32_t r;
    asm("cvt.rna.tf32.f32 %0, %1;" : "=r"(r) : "f"(f));
    return r;
}
__device__ __forceinline__ void cp16(uint32_t dst, const void* src) {
    asm volatile("cp.async.cg.shared.global [%0], [%1], 16;" :: "r"(dst), "l"(src));
}
__device__ __forceinline__ void mma_tf32(float c[4], const uint32_t a[4], const uint32_t b[2]) {
    asm volatile(
        "mma.sync.aligned.m16n8k8.row.col.f32.tf32.tf32.f32 "
        "{%0,%1,%2,%3}, {%4,%5,%6,%7}, {%8,%9}, {%0,%1,%2,%3};"
        : "+f"(c[0]), "+f"(c[1]), "+f"(c[2]), "+f"(c[3])
        : "r"(a[0]), "r"(a[1]), "r"(a[2]), "r"(a[3]), "r"(b[0]), "r"(b[1]));
}

__global__ void spconv_zero_kernel(float4* __restrict__ out, int n4) {
    int i = blockIdx.x * blockDim.x + threadIdx.x;
    if (i < n4) out[i] = make_float4(0.f, 0.f, 0.f, 0.f);
}

__global__ __launch_bounds__(NTHREADS, 4)
void spconv_pers_kernel(const float* __restrict__ feats,
                        const float* __restrict__ kern,
                        const int*   __restrict__ in_map,
                        const int*   __restrict__ out_map,
                        float*       __restrict__ out)
{
    extern __shared__ uint32_t sh[];
    const uint32_t shb = (uint32_t)__cvta_generic_to_shared(sh);

    const int tid = threadIdx.x;
    const int wid = tid >> 5;
    const int lid = tid & 31;
    const int cta = blockIdx.x;

    const int t0  = cta * QT + (cta < RT ? cta : RT);
    const int cnt = QT + (cta < RT ? 1 : 0);
    const int S   = cnt * 4;                   // 4 quarter-stages per tile

    const int g = lid >> 2, t = lid & 3;
    const int rgrpw = wid >> 1, chalf = wid & 1;
    const int mbase = rgrpw * 32;

    // ---- Prologue: fetch idx/omap for tile t0 into slot 0 ----
    {
        int tt = t0;
        int k0 = tt / TPK, m00 = (tt % TPK) * TILE_M;
        if (tid < 32) {
            int m = m00 + tid * 4;
            if (m < MPAIRS)
                cp16(shb + (OFF_IDX + tid * 4) * 4, in_map + (size_t)k0 * MPAIRS + m);
        } else if (tid < 64) {
            int ci = tid - 32, m = m00 + ci * 4;
            if (m < MPAIRS)
                cp16(shb + (OFF_OMAP + ci * 4) * 4, out_map + (size_t)k0 * MPAIRS + m);
        }
        asm volatile("cp.async.commit_group;" ::: "memory");
        asm volatile("cp.async.wait_group 0;" ::: "memory");
        __syncthreads();
    }

    // Gathers the A quarter-tile (k-cols [16q,16q+16)) for stage sp into buffer
    // sp%3; q==0 stages also prefetch idx/omap for tile li+1 (ring slot %3).
    auto issue_stage = [&](int sp) {
        int li = sp >> 2, q = sp & 3;
        int tt = t0 + li;
        int m0 = (tt % TPK) * TILE_M;
        int slot = li % 3;
        uint32_t abase = shb + ((sp % 3) * ABUF_WORDS) * 4;
        #pragma unroll
        for (int j = 0; j < 2; ++j) {
            int cch = tid + j * NTHREADS;
            int row = cch >> 2, ch = cch & 3;   // 4 chunks of 16B per row
            int m = m0 + row;
            int gi = (int)sh[OFF_IDX + slot * TILE_M + row];
            int srow = (m < MPAIRS) ? gi : 0;
            cp16(abase + (row * ASTRIDE + ch * 4) * 4,
                 feats + (size_t)srow * CIN + q * 16 + ch * 4);
        }
        if (q == 0 && li + 1 < cnt) {
            int tt2 = tt + 1;
            int k2 = tt2 / TPK, m02 = (tt2 % TPK) * TILE_M;
            int slot2 = (li + 1) % 3;
            if (tid < 32) {
                int m = m02 + tid * 4;
                if (m < MPAIRS)
                    cp16(shb + (OFF_IDX + slot2 * TILE_M + tid * 4) * 4,
                         in_map + (size_t)k2 * MPAIRS + m);
            } else if (tid < 64) {
                int ci = tid - 32, m = m02 + ci * 4;
                if (m < MPAIRS)
                    cp16(shb + (OFF_OMAP + slot2 * TILE_M + ci * 4) * 4,
                         out_map + (size_t)k2 * MPAIRS + m);
            }
        }
        asm volatile("cp.async.commit_group;" ::: "memory");
    };

    issue_stage(0);
    issue_stage(1);

    float acc[2][4][4];
    int cur_k = -1;

    for (int s = 0; s < S; ++s) {
        // Outstanding groups here: {s, s+1}. Retire group s (keep s+1 in
        // flight); final iteration drains everything.
        if (s + 1 < S) {
            asm volatile("cp.async.wait_group 1;" ::: "memory");
        } else {
            asm volatile("cp.async.wait_group 0;" ::: "memory");
        }
        __syncthreads();   // publish buffer s%3; frees buffer (s+2)%3

        if (s + 2 < S) issue_stage(s + 2);

        const int li = s >> 2, q = s & 3;
        const int tt = t0 + li;
        const int kk = tt / TPK;
        const int m0 = (tt % TPK) * TILE_M;

        if (q == 0) {
            if (kk != cur_k) {
                // ---- Stage B = W[kk]^T, fragment-packed, cout rows permuted ----
                const float* W = kern + (size_t)kk * CIN * COUT;
                #pragma unroll
                for (int idx = tid; idx < CIN * COUT; idx += NTHREADS) {
                    int i = idx >> 6;              // cin
                    int o = idx & 63;              // cout
                    int P = o >> 4, local = o & 15;
                    int ttq = local >> 2, rr = local & 3;
                    int pos = (2 * P + (rr >> 1)) * 8 + 2 * ttq + (rr & 1);
                    int nt = pos >> 3, gg = pos & 7;
                    int si = i >> 3, j = i & 7;
                    int tj = j & 3, e = j >> 2;
                    sh[OFF_B + (((nt * 8 + si) * 32) + gg * 4 + tj) * 2 + e] = f2tf32(W[idx]);
                }
                cur_k = kk;
                __syncthreads();
            }
            #pragma unroll
            for (int mt = 0; mt < 2; ++mt)
                #pragma unroll
                for (int nt = 0; nt < 4; ++nt)
                    #pragma unroll
                    for (int e = 0; e < 4; ++e) acc[mt][nt][e] = 0.f;
        }

        // ---- GEMM: 2 k-steps over this quarter-buffer (raw fp32 -> RNA tf32) ----
        const uint32_t* Abuf = sh + (s % 3) * ABUF_WORDS;
        #pragma unroll
        for (int sl = 0; sl < 2; ++sl) {
            const int sg = q * 2 + sl;
            uint32_t af[2][4];
            #pragma unroll
            for (int mt = 0; mt < 2; ++mt) {
                const uint32_t* ap = Abuf + (mbase + mt * 16 + g) * ASTRIDE + sl * 8 + t;
                af[mt][0] = f2tf32(__uint_as_float(ap[0]));
                af[mt][1] = f2tf32(__uint_as_float(ap[8 * ASTRIDE]));
                af[mt][2] = f2tf32(__uint_as_float(ap[4]));
                af[mt][3] = f2tf32(__uint_as_float(ap[8 * ASTRIDE + 4]));
            }
            #pragma unroll
            for (int nt = 0; nt < 4; ++nt) {
                const int nb = chalf * 4 + nt;
                uint32_t bf[2];
                uint32_t baddr = shb + (OFF_B + ((nb * 8 + sg) * 32 + lid) * 2) * 4;
                asm volatile("ld.shared.v2.b32 {%0, %1}, [%2];"
                             : "=r"(bf[0]), "=r"(bf[1]) : "r"(baddr));
                mma_tf32(acc[0][nt], af[0], bf);
                mma_tf32(acc[1][nt], af[1], bf);
            }
        }

        if (q == 3) {
            // ---- Scatter: v4 global reductions, 4 contiguous couts each ----
            const int slot = li % 3;
            #pragma unroll
            for (int mt = 0; mt < 2; ++mt) {
                #pragma unroll
                for (int half = 0; half < 2; ++half) {
                    int ml = mbase + mt * 16 + g + half * 8;
                    int m = m0 + ml;
                    if (m < MPAIRS) {
                        int orow = (int)sh[OFF_OMAP + slot * TILE_M + ml];
                        float* dst = out + (size_t)orow * COUT + t * 4;
                        #pragma unroll
                        for (int pp = 0; pp < 2; ++pp) {
                            int P = chalf * 2 + pp;
                            asm volatile("red.global.add.v4.f32 [%0], {%1,%2,%3,%4};"
                                         :: "l"(dst + 16 * P),
                                            "f"(acc[mt][2 * pp][half * 2]),
                                            "f"(acc[mt][2 * pp][half * 2 + 1]),
                                            "f"(acc[mt][2 * pp + 1][half * 2]),
                                            "f"(acc[mt][2 * pp + 1][half * 2 + 1]) : "memory");
                        }
                    }
                }
            }
        }
    }
}

extern "C" void kernel_launch(void* const* d_in, const int* in_sizes, int n_in,
                              void* d_out, int out_size) {
    const float* feats   = (const float*)d_in[0];   // [N, 64]
    const float* kern    = (const float*)d_in[1];   // [27, 64, 64]
    const int*   in_map  = (const int*)d_in[2];     // [27, 50000]
    const int*   out_map = (const int*)d_in[3];     // [27, 50000]
    float* out = (float*)d_out;                     // [N, 64]

    int n4 = NVOX * COUT / 4;
    spconv_zero_kernel<<<(n4 + 255) / 256, 256>>>((float4*)out, n4);

    int smem_bytes = SMEM_WORDS * (int)sizeof(uint32_t);   // 50176 B -> 4 CTAs/SM
    cudaFuncSetAttribute(spconv_pers_kernel,
                         cudaFuncAttributeMaxDynamicSharedMemorySize, smem_bytes);
    spconv_pers_kernel<<<NCTA, NTHREADS, smem_bytes>>>(feats, kern, in_map, out_map, out);
}

// round 12
// speedup vs baseline: 1.0062x; 1.0062x over previous
#include <cuda_runtime.h>
#include <cstdint>

// Sparse 3D conv, persistent-CTA pipelined (mma.sync tf32; tcgen05 PTX rejected
// by harness's compute_103 target).
// out[out_map[k,m]] += feats[in_map[k,m]] @ kernel[k]
// N=200000, K=27, M=50000, Cin=Cout=64, fp32 in/out, tf32(RNA at LDS) MMA.
//
// R11 = R9 structure (half-tile stages, 2 buffers, 4 CTAs/SM) + k-permuted
// fragment layouts: A pairs via LDS.64 (rotated-chunk smem layout), B quads
// via LDS.128. ~21% fewer issue ops per stage, identical math.

#define KOFF    27
#define MPAIRS  50000
#define NVOX    200000
#define CIN     64
#define COUT    64
#define TILE_M  128
#define NTHREADS 256
#define TPK     391                 // ceil(50000/128)
#define NTILES  (KOFF * TPK)        // 10557
#define NCTA    608                 // 4 per SM
#define QT      17                  // 10557 = 608*17 + 221
#define RT      221
#define ASTRIDE 36                  // words per row (32 data + 4 pad)

#define ABUF_WORDS (TILE_M * ASTRIDE)          // 4608 words per buffer
#define OFF_B      (2 * ABUF_WORDS)            // 9216: fragment-packed W^T (4096 w)
#define OFF_IDX    (OFF_B + CIN * COUT)        // 13312: IDX[3][128]
#define OFF_OMAP   (OFF_IDX + 3 * TILE_M)      // 13696: OMAP[3][128]
#define SMEM_WORDS (OFF_OMAP + 3 * TILE_M)     // 14080 words = 56320 B

__device__ __forceinline__ uint32_t f2tf32(float f) {
    uint32_t r;
    asm("cvt.rna.tf32.f32 %0, %1;" : "=r"(r) : "f"(f));
    return r;
}
__device__ __forceinline__ void cp16(uint32_t dst, const void* src) {
    asm volatile("cp.async.cg.shared.global [%0], [%1], 16;" :: "r"(dst), "l"(src));
}
__device__ __forceinline__ void mma_tf32(float c[4], const uint32_t a[4], const uint32_t b[2]) {
    asm volatile(
        "mma.sync.aligned.m16n8k8.row.col.f32.tf32.tf32.f32 "
        "{%0,%1,%2,%3}, {%4,%5,%6,%7}, {%8,%9}, {%0,%1,%2,%3};"
        : "+f"(c[0]), "+f"(c[1]), "+f"(c[2]), "+f"(c[3])
        : "r"(a[0]), "r"(a[1]), "r"(a[2]), "r"(a[3]), "r"(b[0]), "r"(b[1]));
}

__global__ void spconv_zero_kernel(float4* __restrict__ out, int n4) {
    int i = blockIdx.x * blockDim.x + threadIdx.x;
    if (i < n4) out[i] = make_float4(0.f, 0.f, 0.f, 0.f);
}

__global__ __launch_bounds__(NTHREADS, 4)
void spconv_pers_kernel(const float* __restrict__ feats,
                        const float* __restrict__ kern,
                        const int*   __restrict__ in_map,
                        const int*   __restrict__ out_map,
                        float*       __restrict__ out)
{
    extern __shared__ uint32_t sh[];
    const uint32_t shb = (uint32_t)__cvta_generic_to_shared(sh);

    const int tid = threadIdx.x;
    const int wid = tid >> 5;
    const int lid = tid & 31;
    const int cta = blockIdx.x;

    const int t0  = cta * QT + (cta < RT ? cta : RT);
    const int cnt = QT + (cta < RT ? 1 : 0);
    const int S   = cnt * 2;

    const int g = lid >> 2, t = lid & 3;
    const int rgrpw = wid >> 1, chalf = wid & 1;
    const int mbase = rgrpw * 32;

    // ---- Prologue: fetch idx/omap for tile t0 into slot 0 ----
    {
        int tt = t0;
        int k0 = tt / TPK, m00 = (tt % TPK) * TILE_M;
        if (tid < 32) {
            int m = m00 + tid * 4;
            if (m < MPAIRS)
                cp16(shb + (OFF_IDX + tid * 4) * 4, in_map + (size_t)k0 * MPAIRS + m);
        } else if (tid < 64) {
            int ci = tid - 32, m = m00 + ci * 4;
            if (m < MPAIRS)
                cp16(shb + (OFF_OMAP + ci * 4) * 4, out_map + (size_t)k0 * MPAIRS + m);
        }
        asm volatile("cp.async.commit_group;" ::: "memory");
        asm volatile("cp.async.wait_group 0;" ::: "memory");
        __syncthreads();
    }

    // A half-tile gather: chunk ch of row r stored at rotated chunk (ch+r)&7.
    auto issue_stage = [&](int sp) {
        int li = sp >> 1, h = sp & 1;
        int tt = t0 + li;
        int m0 = (tt % TPK) * TILE_M;
        int slot = li % 3;
        uint32_t abase = shb + ((sp & 1) * ABUF_WORDS) * 4;
        #pragma unroll
        for (int j = 0; j < 2; ++j) {
            int cch = tid + j * NTHREADS;
            int row = cch >> 2, ch2 = cch & 3;           // 2 sweeps x 4 chunks? no:
            (void)ch2;
            row = cch >> 3; int ch = cch & 7;            // 8 chunks of 16B per row... half-tile=32 cols=8 chunks
            // NOTE: half-tile has 32 cols = 8 chunks; 128 rows x 8 = 1024 ops over 2 sweeps of 512? Only 256 thr x 2 = 512.
            // Use 2 chunk-groups per thread instead:
            int m = m0 + row;
            int gi = (int)sh[OFF_IDX + slot * TILE_M + row];
            int srow = (m < MPAIRS) ? gi : 0;
            int chr = (ch + row) & 7;
            cp16(abase + (row * ASTRIDE + chr * 4) * 4,
                 feats + (size_t)srow * CIN + h * 32 + ch * 4);
            // second half of rows
            int cch2 = cch + 2 * NTHREADS;
            int row2 = cch2 >> 3, chb = cch2 & 7;
            int m2 = m0 + row2;
            int gi2 = (int)sh[OFF_IDX + slot * TILE_M + row2];
            int srow2 = (m2 < MPAIRS) ? gi2 : 0;
            int chr2 = (chb + row2) & 7;
            cp16(abase + (row2 * ASTRIDE + chr2 * 4) * 4,
                 feats + (size_t)srow2 * CIN + h * 32 + chb * 4);
        }
        if (h == 0 && li + 1 < cnt) {
            int tt2 = tt + 1;
            int k2 = tt2 / TPK, m02 = (tt2 % TPK) * TILE_M;
            int slot2 = (li + 1) % 3;
            if (tid < 32) {
                int m = m02 + tid * 4;
                if (m < MPAIRS)
                    cp16(shb + (OFF_IDX + slot2 * TILE_M + tid * 4) * 4,
                         in_map + (size_t)k2 * MPAIRS + m);
            } else if (tid < 64) {
                int ci = tid - 32, m = m02 + ci * 4;
                if (m < MPAIRS)
                    cp16(shb + (OFF_OMAP + slot2 * TILE_M + ci * 4) * 4,
                         out_map + (size_t)k2 * MPAIRS + m);
            }
        }
        asm volatile("cp.async.commit_group;" ::: "memory");
    };

    issue_stage(0);

    float acc[2][4][4];
    int cur_k = -1;

    for (int s = 0; s < S; ++s) {
        asm volatile("cp.async.wait_group 0;" ::: "memory");
        __syncthreads();   // publish buffer s%2; frees buffer (s+1)%2

        if (s + 1 < S) issue_stage(s + 1);

        const int li = s >> 1, h = s & 1;
        const int tt = t0 + li;
        const int kk = tt / TPK;
        const int m0 = (tt % TPK) * TILE_M;

        if (h == 0) {
            if (kk != cur_k) {
                // ---- Stage B = W[kk]^T, LDS.128-quad packed, cout perm ----
                // k remap within 8-window: raw col rem=2t+e <-> logical t,t+4e.
                const float* W = kern + (size_t)kk * CIN * COUT;
                #pragma unroll
                for (int idx = tid; idx < CIN * COUT; idx += NTHREADS) {
                    int i = idx >> 6;              // cin
                    int o = idx & 63;              // cout
                    int P = o >> 4, local = o & 15;
                    int ttq = local >> 2, rr = local & 3;
                    int pos = (2 * P + (rr >> 1)) * 8 + 2 * ttq + (rr & 1);
                    int nt = pos >> 3, gg = pos & 7;
                    int hi2 = i >> 5, cs = i & 31;
                    int sg = 4 * hi2 + (cs >> 3);
                    int tc = (cs & 7) >> 1, e = cs & 1;
                    sh[OFF_B + ((((nt >> 1) * 8 + sg) * 32) + gg * 4 + tc) * 4
                             + (nt & 1) * 2 + e] = f2tf32(W[idx]);
                }
                cur_k = kk;
                __syncthreads();
            }
            #pragma unroll
            for (int mt = 0; mt < 2; ++mt)
                #pragma unroll
                for (int nt = 0; nt < 4; ++nt)
                    #pragma unroll
                    for (int e = 0; e < 4; ++e) acc[mt][nt][e] = 0.f;
        }

        // ---- GEMM: 4 k-steps (A pairs LDS.64, B quads LDS.128, RNA tf32) ----
        const uint32_t abase = shb + ((s & 1) * ABUF_WORDS) * 4;
        #pragma unroll
        for (int sl = 0; sl < 4; ++sl) {
            const int sg = h * 4 + sl;
            uint32_t af[2][4];
            #pragma unroll
            for (int mt = 0; mt < 2; ++mt) {
                #pragma unroll
                for (int rh = 0; rh < 2; ++rh) {
                    int r = mbase + mt * 16 + g + rh * 8;
                    int chr = (2 * sl + (t >> 1) + r) & 7;
                    uint32_t addr = abase + (r * ASTRIDE + chr * 4 + 2 * (t & 1)) * 4;
                    uint32_t lo, hi;
                    asm volatile("ld.shared.v2.b32 {%0,%1}, [%2];"
                                 : "=r"(lo), "=r"(hi) : "r"(addr));
                    af[mt][0 + rh] = f2tf32(__uint_as_float(lo));
                    af[mt][2 + rh] = f2tf32(__uint_as_float(hi));
                }
            }
            #pragma unroll
            for (int ntq = 0; ntq < 2; ++ntq) {
                int ntp = chalf * 2 + ntq;
                uint32_t baddr = shb + (OFF_B + ((ntp * 8 + sg) * 32 + lid) * 4) * 4;
                uint32_t b0, b1, b2, b3;
                asm volatile("ld.shared.v4.b32 {%0,%1,%2,%3}, [%4];"
                             : "=r"(b0), "=r"(b1), "=r"(b2), "=r"(b3) : "r"(baddr));
                uint32_t bfa[2] = {b0, b1};
                uint32_t bfb[2] = {b2, b3};
                mma_tf32(acc[0][2 * ntq],     af[0], bfa);
                mma_tf32(acc[1][2 * ntq],     af[1], bfa);
                mma_tf32(acc[0][2 * ntq + 1], af[0], bfb);
                mma_tf32(acc[1][2 * ntq + 1], af[1], bfb);
            }
        }

        if (h == 1) {
            // ---- Scatter: v4 global reductions, 4 contiguous couts each ----
            const int slot = li % 3;
            #pragma unroll
            for (int mt = 0; mt < 2; ++mt) {
                #pragma unroll
                for (int half = 0; half < 2; ++half) {
                    int ml = mbase + mt * 16 + g + half * 8;
                    int m = m0 + ml;
                    if (m < MPAIRS) {
                        int orow = (int)sh[OFF_OMAP + slot * TILE_M + ml];
                        float* dst = out + (size_t)orow * COUT + t * 4;
                        #pragma unroll
                        for (int pp = 0; pp < 2; ++pp) {
                            int P = chalf * 2 + pp;
                            asm volatile("red.global.add.v4.f32 [%0], {%1,%2,%3,%4};"
                                         :: "l"(dst + 16 * P),
                                            "f"(acc[mt][2 * pp][half * 2]),
                                            "f"(acc[mt][2 * pp][half * 2 + 1]),
                                            "f"(acc[mt][2 * pp + 1][half * 2]),
                                            "f"(acc[mt][2 * pp + 1][half * 2 + 1]) : "memory");
                        }
                    }
                }
            }
        }
    }
}

extern "C" void kernel_launch(void* const* d_in, const int* in_sizes, int n_in,
                              void* d_out, int out_size) {
    const float* feats   = (const float*)d_in[0];   // [N, 64]
    const float* kern    = (const float*)d_in[1];   // [27, 64, 64]
    const int*   in_map  = (const int*)d_in[2];     // [27, 50000]
    const int*   out_map = (const int*)d_in[3];     // [27, 50000]
    float* out = (float*)d_out;                     // [N, 64]

    int n4 = NVOX * COUT / 4;
    spconv_zero_kernel<<<(n4 + 255) / 256, 256>>>((float4*)out, n4);

    int smem_bytes = SMEM_WORDS * (int)sizeof(uint32_t);   // 56320 B -> 4 CTAs/SM
    cudaFuncSetAttribute(spconv_pers_kernel,
                         cudaFuncAttributeMaxDynamicSharedMemorySize, smem_bytes);
    spconv_pers_kernel<<<NCTA, NTHREADS, smem_bytes>>>(feats, kern, in_map, out_map, out);
}

// round 13
// speedup vs baseline: 1.1401x; 1.1331x over previous
#include <cuda_runtime.h>
#include <cstdint>

// Sparse 3D conv, persistent-CTA pipelined (mma.sync tf32; tcgen05 PTX rejected
// by harness's compute_103 target).
// out[out_map[k,m]] += feats[in_map[k,m]] @ kernel[k]
// N=200000, K=27, M=50000, Cin=Cout=64, fp32 in/out, tf32(RNA at LDS) MMA.
//
// R12 = R9 math/layout + pair-decoupled pipelines: each warp pair (64 threads)
// owns 32 A-rows and runs a private gather->compute pipeline with named
// bar.sync(id,64); idx/omap ring prefetch is pair-private. CTA-wide barriers
// only on (rare) B restage.

#define KOFF    27
#define MPAIRS  50000
#define NVOX    200000
#define CIN     64
#define COUT    64
#define TILE_M  128
#define NTHREADS 256
#define TPK     391                 // ceil(50000/128)
#define NTILES  (KOFF * TPK)        // 10557
#define NCTA    608                 // 4 per SM
#define QT      17                  // 10557 = 608*17 + 221
#define RT      221
#define ASTRIDE 36                  // words per row (32 data + 4 pad)

#define ABUF_WORDS (TILE_M * ASTRIDE)          // 4608 words per buffer
#define OFF_B      (2 * ABUF_WORDS)            // 9216: fragment-packed W^T (4096 w)
#define OFF_IDX    (OFF_B + CIN * COUT)        // 13312: IDX[3][128]
#define OFF_OMAP   (OFF_IDX + 3 * TILE_M)      // 13696: OMAP[3][128]
#define SMEM_WORDS (OFF_OMAP + 3 * TILE_M)     // 14080 words = 56320 B

__device__ __forceinline__ uint32_t f2tf32(float f) {
    uint32_t r;
    asm("cvt.rna.tf32.f32 %0, %1;" : "=r"(r) : "f"(f));
    return r;
}
__device__ __forceinline__ void cp16(uint32_t dst, const void* src) {
    asm volatile("cp.async.cg.shared.global [%0], [%1], 16;" :: "r"(dst), "l"(src));
}
__device__ __forceinline__ void pair_bar(int id) {
    asm volatile("bar.sync %0, 64;" :: "r"(id) : "memory");
}
__device__ __forceinline__ void mma_tf32(float c[4], const uint32_t a[4], const uint32_t b[2]) {
    asm volatile(
        "mma.sync.aligned.m16n8k8.row.col.f32.tf32.tf32.f32 "
        "{%0,%1,%2,%3}, {%4,%5,%6,%7}, {%8,%9}, {%0,%1,%2,%3};"
        : "+f"(c[0]), "+f"(c[1]), "+f"(c[2]), "+f"(c[3])
        : "r"(a[0]), "r"(a[1]), "r"(a[2]), "r"(a[3]), "r"(b[0]), "r"(b[1]));
}

__global__ void spconv_zero_kernel(float4* __restrict__ out, int n4) {
    int i = blockIdx.x * blockDim.x + threadIdx.x;
    if (i < n4) out[i] = make_float4(0.f, 0.f, 0.f, 0.f);
}

__global__ __launch_bounds__(NTHREADS, 4)
void spconv_pers_kernel(const float* __restrict__ feats,
                        const float* __restrict__ kern,
                        const int*   __restrict__ in_map,
                        const int*   __restrict__ out_map,
                        float*       __restrict__ out)
{
    extern __shared__ uint32_t sh[];
    const uint32_t shb = (uint32_t)__cvta_generic_to_shared(sh);

    const int tid = threadIdx.x;
    const int wid = tid >> 5;
    const int lid = tid & 31;
    const int cta = blockIdx.x;

    const int t0  = cta * QT + (cta < RT ? cta : RT);
    const int cnt = QT + (cta < RT ? 1 : 0);
    const int S   = cnt * 2;

    const int g = lid >> 2, t = lid & 3;
    const int rgrpw = wid >> 1, chalf = wid & 1;
    const int mbase = rgrpw * 32;              // pair's 32-row segment base
    const int pt    = tid & 63;                // thread index within pair
    const int barid = rgrpw + 1;               // named barrier per pair (1..4)

    // ---- Prologue: each pair fetches its idx/omap segment of tile t0 ----
    {
        int k0 = t0 / TPK, m00 = (t0 % TPK) * TILE_M;
        if (pt < 8) {
            int m = m00 + mbase + pt * 4;
            if (m < MPAIRS)
                cp16(shb + (OFF_IDX + mbase + pt * 4) * 4,
                     in_map + (size_t)k0 * MPAIRS + m);
        } else if (pt < 16) {
            int ci = pt - 8;
            int m = m00 + mbase + ci * 4;
            if (m < MPAIRS)
                cp16(shb + (OFF_OMAP + mbase + ci * 4) * 4,
                     out_map + (size_t)k0 * MPAIRS + m);
        }
        asm volatile("cp.async.commit_group;" ::: "memory");
        asm volatile("cp.async.wait_group 0;" ::: "memory");
        pair_bar(barid);
    }

    // Pair-private gather of the pair's 32 rows for stage sp (half-tile,
    // k-cols [32h, 32h+32)); h==0 stages also prefetch the pair's idx/omap
    // segment for tile li+1 into ring slot (li+1)%3.
    auto issue_stage = [&](int sp) {
        int li = sp >> 1, h = sp & 1;
        int tt = t0 + li;
        int m0 = (tt % TPK) * TILE_M;
        int slot = li % 3;
        uint32_t abase = shb + ((sp & 1) * ABUF_WORDS) * 4;
        #pragma unroll
        for (int j = 0; j < 4; ++j) {
            int cch = pt + j * 64;             // 0..255 = 32 rows x 8 chunks
            int rl = cch >> 3, ch = cch & 7;
            int row = mbase + rl;
            int m = m0 + row;
            int gi = (int)sh[OFF_IDX + slot * TILE_M + row];
            int srow = (m < MPAIRS) ? gi : 0;
            cp16(abase + (row * ASTRIDE + ch * 4) * 4,
                 feats + (size_t)srow * CIN + h * 32 + ch * 4);
        }
        if (h == 0 && li + 1 < cnt) {
            int tt2 = tt + 1;
            int k2 = tt2 / TPK, m02 = (tt2 % TPK) * TILE_M;
            int slot2 = (li + 1) % 3;
            if (pt < 8) {
                int m = m02 + mbase + pt * 4;
                if (m < MPAIRS)
                    cp16(shb + (OFF_IDX + slot2 * TILE_M + mbase + pt * 4) * 4,
                         in_map + (size_t)k2 * MPAIRS + m);
            } else if (pt < 16) {
                int ci = pt - 8;
                int m = m02 + mbase + ci * 4;
                if (m < MPAIRS)
                    cp16(shb + (OFF_OMAP + slot2 * TILE_M + mbase + ci * 4) * 4,
                         out_map + (size_t)k2 * MPAIRS + m);
            }
        }
        asm volatile("cp.async.commit_group;" ::: "memory");
    };

    issue_stage(0);

    float acc[2][4][4];
    int cur_k = -1;

    for (int s = 0; s < S; ++s) {
        // Retire this pair's group s; pair-bar publishes the pair's A segment
        // (and any idx/omap ring writes) and frees buffer (s+1)%2 pair-locally.
        asm volatile("cp.async.wait_group 0;" ::: "memory");
        pair_bar(barid);

        const int li = s >> 1, h = s & 1;
        const int tt = t0 + li;
        const int kk = tt / TPK;
        const int m0 = (tt % TPK) * TILE_M;

        if (h == 0) {
            if (kk != cur_k) {
                // ---- Rare CTA-wide B restage (uniform condition) ----
                __syncthreads();   // all pairs done reading old B
                const float* W = kern + (size_t)kk * CIN * COUT;
                #pragma unroll
                for (int idx = tid; idx < CIN * COUT; idx += NTHREADS) {
                    int i = idx >> 6;              // cin
                    int o = idx & 63;              // cout
                    int P = o >> 4, local = o & 15;
                    int ttq = local >> 2, rr = local & 3;
                    int pos = (2 * P + (rr >> 1)) * 8 + 2 * ttq + (rr & 1);
                    int nt = pos >> 3, gg = pos & 7;
                    int si = i >> 3, j = i & 7;
                    int tj = j & 3, e = j >> 2;
                    sh[OFF_B + (((nt * 8 + si) * 32) + gg * 4 + tj) * 2 + e] = f2tf32(W[idx]);
                }
                cur_k = kk;
                __syncthreads();
            }
            #pragma unroll
            for (int mt = 0; mt < 2; ++mt)
                #pragma unroll
                for (int nt = 0; nt < 4; ++nt)
                    #pragma unroll
                    for (int e = 0; e < 4; ++e) acc[mt][nt][e] = 0.f;
        }

        if (s + 1 < S) issue_stage(s + 1);

        // ---- GEMM: 4 k-steps over this half-buffer (raw fp32 -> RNA tf32) ----
        const uint32_t* Abuf = sh + (s & 1) * ABUF_WORDS;
        #pragma unroll
        for (int sl = 0; sl < 4; ++sl) {
            const int sg = h * 4 + sl;
            uint32_t af[2][4];
            #pragma unroll
            for (int mt = 0; mt < 2; ++mt) {
                const uint32_t* ap = Abuf + (mbase + mt * 16 + g) * ASTRIDE + sl * 8 + t;
                af[mt][0] = f2tf32(__uint_as_float(ap[0]));
                af[mt][1] = f2tf32(__uint_as_float(ap[8 * ASTRIDE]));
                af[mt][2] = f2tf32(__uint_as_float(ap[4]));
                af[mt][3] = f2tf32(__uint_as_float(ap[8 * ASTRIDE + 4]));
            }
            #pragma unroll
            for (int nt = 0; nt < 4; ++nt) {
                const int nb = chalf * 4 + nt;
                uint32_t bf[2];
                uint32_t baddr = shb + (OFF_B + ((nb * 8 + sg) * 32 + lid) * 2) * 4;
                asm volatile("ld.shared.v2.b32 {%0, %1}, [%2];"
                             : "=r"(bf[0]), "=r"(bf[1]) : "r"(baddr));
                mma_tf32(acc[0][nt], af[0], bf);
                mma_tf32(acc[1][nt], af[1], bf);
            }
        }

        if (h == 1) {
            // ---- Scatter: v4 global reductions, 4 contiguous couts each ----
            const int slot = li % 3;
            #pragma unroll
            for (int mt = 0; mt < 2; ++mt) {
                #pragma unroll
                for (int half = 0; half < 2; ++half) {
                    int ml = mbase + mt * 16 + g + half * 8;
                    int m = m0 + ml;
                    if (m < MPAIRS) {
                        int orow = (int)sh[OFF_OMAP + slot * TILE_M + ml];
                        float* dst = out + (size_t)orow * COUT + t * 4;
                        #pragma unroll
                        for (int pp = 0; pp < 2; ++pp) {
                            int P = chalf * 2 + pp;
                            asm volatile("red.global.add.v4.f32 [%0], {%1,%2,%3,%4};"
                                         :: "l"(dst + 16 * P),
                                            "f"(acc[mt][2 * pp][half * 2]),
                                            "f"(acc[mt][2 * pp][half * 2 + 1]),
                                            "f"(acc[mt][2 * pp + 1][half * 2]),
                                            "f"(acc[mt][2 * pp + 1][half * 2 + 1]) : "memory");
                        }
                    }
                }
            }
        }
    }
}

extern "C" void kernel_launch(void* const* d_in, const int* in_sizes, int n_in,
                              void* d_out, int out_size) {
    const float* feats   = (const float*)d_in[0];   // [N, 64]
    const float* kern    = (const float*)d_in[1];   // [27, 64, 64]
    const int*   in_map  = (const int*)d_in[2];     // [27, 50000]
    const int*   out_map = (const int*)d_in[3];     // [27, 50000]
    float* out = (float*)d_out;                     // [N, 64]

    int n4 = NVOX * COUT / 4;
    spconv_zero_kernel<<<(n4 + 255) / 256, 256>>>((float4*)out, n4);

    int smem_bytes = SMEM_WORDS * (int)sizeof(uint32_t);   // 56320 B -> 4 CTAs/SM
    cudaFuncSetAttribute(spconv_pers_kernel,
                         cudaFuncAttributeMaxDynamicSharedMemorySize, smem_bytes);
    spconv_pers_kernel<<<NCTA, NTHREADS, smem_bytes>>>(feats, kern, in_map, out_map, out);
}